// round 2
// baseline (speedup 1.0000x reference)
#include <cuda_runtime.h>
#include <math.h>
#include <float.h>

#define N_NODES 100000
#define N_EDGES 1600000
#define DIM 128
#define NB 128
#define NEG 0.01f
#define SCAN_BLOCKS 98   // ceil(100000/1024)

// ---------------- scratch (static device globals; no allocation) ----------------
__device__ float g_agg[2][N_NODES * DIM];   // aggregated x (GEMM input), per branch
__device__ float g_dinv[2][N_NODES];
__device__ int   g_deg[2][N_NODES];         // zeroed via one contiguous memset
__device__ int   g_offs[2][N_NODES + 1];
__device__ int   g_cursor[2][N_NODES];
__device__ int   g_csr[2][N_EDGES];         // source node per CSR slot (dest-sorted)
__device__ int   g_bsum[2][128];            // scan spine
__device__ float g_pool[2 * NB * DIM];      // segment_max pools, both branches
__device__ float g_gp[2 * NB * DIM];        // after fc_p + lrelu
__device__ float g_c1[NB * 256];
__device__ float g_c2[NB * 64];

__device__ __forceinline__ float lrelu(float v) { return v >= 0.f ? v : NEG * v; }

__device__ __forceinline__ void atomicMaxFloat(float* addr, float v) {
    if (v >= 0.f) atomicMax((int*)addr, __float_as_int(v));
    else          atomicMin((unsigned int*)addr, __float_as_uint(v));
}

// ---------------- degree count (both branches: blockIdx.y) ----------------
__global__ void k_count(const int* __restrict__ col0, const int* __restrict__ col1) {
    int p = blockIdx.y;
    const int* col = p ? col1 : col0;
    int e = blockIdx.x * blockDim.x + threadIdx.x;
    if (e < N_EDGES) atomicAdd(&g_deg[p][col[e]], 1);
}

// ---------------- scan stage 1: block-local exclusive scan + dinv ----------------
__global__ void k_scan1() {   // grid (98, 2), block 1024
    __shared__ int sh[1024];
    int p = blockIdx.y;
    int t = threadIdx.x;
    int i = blockIdx.x * 1024 + t;
    int v = (i < N_NODES) ? g_deg[p][i] : 0;
    if (i < N_NODES) g_dinv[p][i] = rsqrtf((float)(v + 1));   // +1 self loop
    sh[t] = v;
    __syncthreads();
    #pragma unroll
    for (int off = 1; off < 1024; off <<= 1) {
        int x = (t >= off) ? sh[t - off] : 0;
        __syncthreads();
        sh[t] += x;
        __syncthreads();
    }
    if (i < N_NODES) g_offs[p][i] = sh[t] - v;        // exclusive
    if (t == 1023) g_bsum[p][blockIdx.x] = sh[t];     // block total
}

// ---------------- scan stage 2: spine scan (one block per branch) ----------------
__global__ void k_scan2() {   // grid 2, block 128
    __shared__ int sh[128];
    int p = blockIdx.x;
    int t = threadIdx.x;
    int v = (t < SCAN_BLOCKS) ? g_bsum[p][t] : 0;
    sh[t] = v;
    __syncthreads();
    #pragma unroll
    for (int off = 1; off < 128; off <<= 1) {
        int x = (t >= off) ? sh[t - off] : 0;
        __syncthreads();
        sh[t] += x;
        __syncthreads();
    }
    if (t < SCAN_BLOCKS) g_bsum[p][t] = sh[t] - v;
}

// ---------------- scan stage 3: add spine, init cursor + pool ----------------
__global__ void k_scan3() {   // grid (98, 2), block 1024
    int p = blockIdx.y;
    int t = threadIdx.x;
    int i = blockIdx.x * 1024 + t;
    if (i < N_NODES) {
        int v = g_offs[p][i] + g_bsum[p][blockIdx.x];
        g_offs[p][i] = v;
        g_cursor[p][i] = v;
    }
    if (i == 0) g_offs[p][N_NODES] = N_EDGES;
    if (i < NB * DIM) g_pool[p * NB * DIM + i] = -FLT_MAX;   // pool init folded in
}

// ---------------- CSR fill ----------------
__global__ void k_fill(const int* __restrict__ row0, const int* __restrict__ col0,
                       const int* __restrict__ row1, const int* __restrict__ col1) {
    int p = blockIdx.y;
    const int* row = p ? row1 : row0;
    const int* col = p ? col1 : col0;
    int e = blockIdx.x * blockDim.x + threadIdx.x;
    if (e < N_EDGES) {
        int d = col[e];
        int pos = atomicAdd(&g_cursor[p][d], 1);
        g_csr[p][pos] = row[e];
    }
}

// ---------------- gather aggregation: one warp per destination node, unroll 4 ----------------
__global__ void k_gather(const float* __restrict__ x0, const float* __restrict__ x1) {
    int p = blockIdx.y;
    const float4* x4 = (const float4*)(p ? x1 : x0);
    const int*    csr  = g_csr[p];
    const float*  dinv = g_dinv[p];

    int gw = (blockIdx.x * blockDim.x + threadIdx.x) >> 5;
    int lane = threadIdx.x & 31;
    if (gw >= N_NODES) return;
    const int i = gw;
    const float di = dinv[i];

    float4 xi = x4[(size_t)i * 32 + lane];
    float w = di * di;                       // self-loop norm
    float4 acc;
    acc.x = w * xi.x; acc.y = w * xi.y; acc.z = w * xi.z; acc.w = w * xi.w;

    int j = g_offs[p][i];
    const int s1 = g_offs[p][i + 1];
    for (; j + 4 <= s1; j += 4) {
        int sa = csr[j], sb = csr[j + 1], sc = csr[j + 2], sd = csr[j + 3];
        float wa = di * dinv[sa], wb = di * dinv[sb], wc = di * dinv[sc], wd = di * dinv[sd];
        float4 xa = x4[(size_t)sa * 32 + lane];
        float4 xb = x4[(size_t)sb * 32 + lane];
        float4 xc = x4[(size_t)sc * 32 + lane];
        float4 xd = x4[(size_t)sd * 32 + lane];
        acc.x += wa * xa.x + wb * xb.x + wc * xc.x + wd * xd.x;
        acc.y += wa * xa.y + wb * xb.y + wc * xc.y + wd * xd.y;
        acc.z += wa * xa.z + wb * xb.z + wc * xc.z + wd * xd.z;
        acc.w += wa * xa.w + wb * xb.w + wc * xc.w + wd * xd.w;
    }
    for (; j < s1; j++) {
        int s = csr[j];
        float ws = di * dinv[s];
        float4 xs = x4[(size_t)s * 32 + lane];
        acc.x += ws * xs.x; acc.y += ws * xs.y; acc.z += ws * xs.z; acc.w += ws * xs.w;
    }
    ((float4*)g_agg[p])[(size_t)i * 32 + lane] = acc;
}

// ---------------- GEMM (agg @ W + b) + lrelu + segment_max epilogue ----------------
// 128x128 tile, BK=32, 256 threads, 8x8 micro-tile. grid (782, 2)
__global__ void k_gemm_pool(const float* __restrict__ W0, const float* __restrict__ b0,
                            const float* __restrict__ W1, const float* __restrict__ b1,
                            const int* __restrict__ batch0, const int* __restrict__ batch1) {
    __shared__ float As[128][33];
    __shared__ float Ws[32][128];
    const int p = blockIdx.y;
    const float* __restrict__ W    = p ? W1 : W0;
    const float* __restrict__ bias = p ? b1 : b0;
    const int*   __restrict__ batch = p ? batch1 : batch0;
    const float* __restrict__ agg  = g_agg[p];
    const int tx = threadIdx.x & 15;
    const int ty = threadIdx.x >> 4;
    const int row0 = blockIdx.x * 128;

    float acc[8][8];
    #pragma unroll
    for (int i = 0; i < 8; i++)
        #pragma unroll
        for (int j = 0; j < 8; j++) acc[i][j] = 0.f;

    for (int kb = 0; kb < 4; kb++) {
        #pragma unroll
        for (int it = 0; it < 4; it++) {
            int flat = threadIdx.x + it * 256;   // float4 index, 1024 total
            int r = flat >> 3, c4 = (flat & 7) * 4;
            int gm = row0 + r;
            float4 v = make_float4(0.f, 0.f, 0.f, 0.f);
            if (gm < N_NODES)
                v = *(const float4*)&agg[(size_t)gm * 128 + kb * 32 + c4];
            As[r][c4 + 0] = v.x; As[r][c4 + 1] = v.y; As[r][c4 + 2] = v.z; As[r][c4 + 3] = v.w;
        }
        #pragma unroll
        for (int it = 0; it < 4; it++) {
            int flat = threadIdx.x + it * 256;
            int r = flat >> 5, c4 = (flat & 31) * 4;
            *(float4*)&Ws[r][c4] = *(const float4*)&W[(size_t)(kb * 32 + r) * 128 + c4];
        }
        __syncthreads();
        #pragma unroll
        for (int k = 0; k < 32; k++) {
            float a[8], b[8];
            #pragma unroll
            for (int j = 0; j < 8; j++) a[j] = As[ty * 8 + j][k];
            #pragma unroll
            for (int j = 0; j < 8; j++) b[j] = Ws[k][tx * 8 + j];
            #pragma unroll
            for (int i = 0; i < 8; i++)
                #pragma unroll
                for (int j = 0; j < 8; j++) acc[i][j] += a[i] * b[j];
        }
        __syncthreads();
    }

    float* pool = &g_pool[p * NB * DIM];
    #pragma unroll
    for (int i = 0; i < 8; i++) {
        int gm = row0 + ty * 8 + i;
        if (gm >= N_NODES) continue;
        int bt = batch[gm];
        float* pr = &pool[bt * DIM];
        #pragma unroll
        for (int j = 0; j < 8; j++) {
            int col = tx * 8 + j;
            float v = lrelu(acc[i][j] + bias[col]);
            atomicMaxFloat(&pr[col], v);
        }
    }
}

// ---------------- tail MLPs (tiny) ----------------
__global__ void k_fcp(const float* __restrict__ W1, const float* __restrict__ b1,
                      const float* __restrict__ W2, const float* __restrict__ b2) {
    int p = blockIdx.y, r = blockIdx.x, d = threadIdx.x;  // 128 threads
    __shared__ float prow[128];
    prow[d] = g_pool[p * NB * DIM + r * 128 + d];
    __syncthreads();
    const float* W = p ? W2 : W1;
    const float* bb = p ? b2 : b1;
    float s = bb[d];
    #pragma unroll 8
    for (int k = 0; k < 128; k++) s += prow[k] * W[k * 128 + d];
    g_gp[p * NB * DIM + r * 128 + d] = lrelu(s);
}

__global__ void k_fc1(const float* __restrict__ W, const float* __restrict__ b) {
    int r = blockIdx.x, d = threadIdx.x;   // 256 threads
    __shared__ float in[256];
    in[d] = (d < 128) ? g_gp[r * 128 + d] : g_gp[NB * DIM + r * 128 + (d - 128)];
    __syncthreads();
    float s = b[d];
    #pragma unroll 8
    for (int k = 0; k < 256; k++) s += in[k] * W[k * 256 + d];
    g_c1[r * 256 + d] = lrelu(s);
}

__global__ void k_fc2(const float* __restrict__ W, const float* __restrict__ b) {
    int r = blockIdx.x, d = threadIdx.x;   // 64 threads
    __shared__ float in[256];
    for (int k = d; k < 256; k += 64) in[k] = g_c1[r * 256 + k];
    __syncthreads();
    float s = b[d];
    #pragma unroll 8
    for (int k = 0; k < 256; k++) s += in[k] * W[k * 64 + d];
    g_c2[r * 64 + d] = lrelu(s);
}

__global__ void k_out(const float* __restrict__ W, const float* __restrict__ b,
                      float* __restrict__ out) {
    int r = threadIdx.x;   // 128 threads, 1 block
    float s = b[0];
    #pragma unroll
    for (int k = 0; k < 64; k++) s += g_c2[r * 64 + k] * W[k];
    out[r] = 1.f / (1.f + expf(-s));
}

// ---------------- host launcher ----------------
extern "C" void kernel_launch(void* const* d_in, const int* in_sizes, int n_in,
                              void* d_out, int out_size) {
    // Resolve the order of the first 6 tensors (dict order vs signature order).
    int ix[2], ie[2], ib[2];
    if (in_sizes[1] == N_NODES * DIM) {
        ix[0] = 0; ix[1] = 1; ie[0] = 2; ie[1] = 3; ib[0] = 4; ib[1] = 5;   // dict order
    } else {
        ix[0] = 0; ie[0] = 1; ib[0] = 2; ix[1] = 3; ie[1] = 4; ib[1] = 5;   // signature order
    }
    const float* x0 = (const float*)d_in[ix[0]];
    const float* x1 = (const float*)d_in[ix[1]];
    const int* row0 = (const int*)d_in[ie[0]];
    const int* col0 = row0 + N_EDGES;
    const int* row1 = (const int*)d_in[ie[1]];
    const int* col1 = row1 + N_EDGES;
    const int* bat0 = (const int*)d_in[ib[0]];
    const int* bat1 = (const int*)d_in[ib[1]];

    const float* convW0 = (const float*)d_in[6];
    const float* convB0 = (const float*)d_in[7];
    const float* convW1 = (const float*)d_in[8];
    const float* convB1 = (const float*)d_in[9];
    const float* fcp1W = (const float*)d_in[10];
    const float* fcp1B = (const float*)d_in[11];
    const float* fcp2W = (const float*)d_in[12];
    const float* fcp2B = (const float*)d_in[13];
    const float* fc1W  = (const float*)d_in[14];
    const float* fc1B  = (const float*)d_in[15];
    const float* fc2W  = (const float*)d_in[16];
    const float* fc2B  = (const float*)d_in[17];
    const float* outW  = (const float*)d_in[18];
    const float* outB  = (const float*)d_in[19];

    // zero both branches' degree arrays with one memset node
    void* degPtr = nullptr;
    cudaGetSymbolAddress(&degPtr, g_deg);
    cudaMemsetAsync(degPtr, 0, 2 * N_NODES * sizeof(int));

    const int EB = (N_EDGES + 255) / 256;
    k_count<<<dim3(EB, 2), 256>>>(col0, col1);
    k_scan1<<<dim3(SCAN_BLOCKS, 2), 1024>>>();
    k_scan2<<<2, 128>>>();
    k_scan3<<<dim3(SCAN_BLOCKS, 2), 1024>>>();
    k_fill<<<dim3(EB, 2), 256>>>(row0, col0, row1, col1);
    k_gather<<<dim3((N_NODES * 32 + 255) / 256, 2), 256>>>(x0, x1);
    k_gemm_pool<<<dim3((N_NODES + 127) / 128, 2), 256>>>(convW0, convB0, convW1, convB1, bat0, bat1);

    k_fcp<<<dim3(NB, 2), 128>>>(fcp1W, fcp1B, fcp2W, fcp2B);
    k_fc1<<<NB, 256>>>(fc1W, fc1B);
    k_fc2<<<NB, 64>>>(fc2W, fc2B);
    k_out<<<1, 128>>>(outW, outB, (float*)d_out);
}

// round 3
// speedup vs baseline: 2.7028x; 2.7028x over previous
#include <cuda_runtime.h>
#include <math.h>
#include <float.h>

#define N_NODES 100000
#define N_EDGES 1600000
#define DIM 128
#define NB 128
#define NEG 0.01f
#define SCAN_BLOCKS 98   // ceil(100000/1024)

// ---------------- scratch (static device globals; no allocation) ----------------
struct Zeroed {                              // zeroed by one cudaMemsetAsync per call
    int deg[2][N_NODES];
    unsigned long long look[2][SCAN_BLOCKS]; // lookback descriptors: (flag<<62)|value
};
__device__ Zeroed g_z;
__device__ float g_agg[2][N_NODES * DIM];
__device__ float g_dinv[2][N_NODES];
__device__ int   g_offs[2][N_NODES + 1];
__device__ int   g_cursor[2][N_NODES];
__device__ int   g_csr[2][N_EDGES];
__device__ float g_pool[2 * NB * DIM];
__device__ float g_gp[2 * NB * DIM];
__device__ float g_c1[NB * 256];
__device__ float g_c2[NB * 64];

__device__ __forceinline__ float lrelu(float v) { return v >= 0.f ? v : NEG * v; }

__device__ __forceinline__ void atomicMaxFloat(float* addr, float v) {
    if (v >= 0.f) atomicMax((int*)addr, __float_as_int(v));
    else          atomicMin((unsigned int*)addr, __float_as_uint(v));
}

// packed f32x2 FMA (SASS FFMA2; ptxas never emits this from C++)
#define FMA_F32X2(d, a, b) asm("fma.rn.f32x2 %0, %1, %2, %0;" : "+l"(d) : "l"(a), "l"(b))

// ---------------- launch 0: degree count ----------------
__global__ void k_count(const int* __restrict__ col0, const int* __restrict__ col1) {
    int p = blockIdx.y;
    const int* col = p ? col1 : col0;
    int e = blockIdx.x * blockDim.x + threadIdx.x;
    if (e < N_EDGES) atomicAdd(&g_z.deg[p][col[e]], 1);
}

// ---------------- launch 1: single-pass scan (decoupled lookback) + dinv + cursor + pool init ----------------
__global__ void k_scan() {   // grid (98, 2), block 1024
    __shared__ int sh[1024];
    __shared__ int sE;
    const int p = blockIdx.y;
    const int b = blockIdx.x;
    const int t = threadIdx.x;
    const int i = b * 1024 + t;
    const int lane = t & 31;

    int v = (i < N_NODES) ? g_z.deg[p][i] : 0;
    if (i < N_NODES) g_dinv[p][i] = rsqrtf((float)(v + 1));   // +1 self loop
    sh[t] = v;
    __syncthreads();
    #pragma unroll
    for (int off = 1; off < 1024; off <<= 1) {
        int x = (t >= off) ? sh[t - off] : 0;
        __syncthreads();
        sh[t] += x;
        __syncthreads();
    }
    const int total = sh[1023];

    // publish aggregate, then warp 0 resolves the exclusive prefix E
    if (b > 0 && t == 0)
        *(volatile unsigned long long*)&g_z.look[p][b] = (1ULL << 62) | (unsigned)total;
    if (t < 32) {   // warp 0
        int E = 0;
        if (b > 0) {
            int base = b - 1;
            int accum = 0;
            bool done = false;
            while (!done) {
                int idx = base - lane;
                unsigned long long w = (idx >= 0)
                    ? *(volatile unsigned long long*)&g_z.look[p][idx]
                    : (2ULL << 62);                      // below 0: prefix 0
                int flg = (int)(w >> 62);
                int val = (int)(w & 0xffffffffULL);
                unsigned m2 = __ballot_sync(0xffffffffu, flg == 2);
                unsigned m1 = __ballot_sync(0xffffffffu, flg >= 1);
                if (m2) {
                    int t2 = __ffs(m2) - 1;              // nearest resolved prefix
                    unsigned below = (t2 == 0) ? 0u : ((1u << t2) - 1u);
                    if ((m1 & below) == below) {
                        int c = (lane <= t2) ? val : 0;  // aggs below + prefix at t2
                        #pragma unroll
                        for (int o = 16; o; o >>= 1) c += __shfl_xor_sync(0xffffffffu, c, o);
                        accum += c;
                        done = true;
                    }
                } else if (m1 == 0xffffffffu) {          // full window of aggregates
                    int c = (idx >= 0) ? val : 0;
                    #pragma unroll
                    for (int o = 16; o; o >>= 1) c += __shfl_xor_sync(0xffffffffu, c, o);
                    accum += c;
                    base -= 32;
                }
            }
            E = accum;
        }
        if (lane == 0) {
            *(volatile unsigned long long*)&g_z.look[p][b] = (2ULL << 62) | (unsigned)(E + total);
            sE = E;
        }
    }
    __syncthreads();
    const int E = sE;

    if (i < N_NODES) {
        int ex = E + sh[t] - v;      // exclusive prefix
        g_offs[p][i] = ex;
        g_cursor[p][i] = ex;
    }
    if (b == 0 && t == 0) g_offs[p][N_NODES] = N_EDGES;
    if (b == 0) {                    // pool init folded in
        #pragma unroll
        for (int it = 0; it < 16; it++)
            g_pool[p * NB * DIM + it * 1024 + t] = -FLT_MAX;
    }
}

// ---------------- launch 2: CSR fill ----------------
__global__ void k_fill(const int* __restrict__ row0, const int* __restrict__ col0,
                       const int* __restrict__ row1, const int* __restrict__ col1) {
    int p = blockIdx.y;
    const int* row = p ? row1 : row0;
    const int* col = p ? col1 : col0;
    int e = blockIdx.x * blockDim.x + threadIdx.x;
    if (e < N_EDGES) {
        int d = col[e];
        int pos = atomicAdd(&g_cursor[p][d], 1);
        g_csr[p][pos] = row[e];
    }
}

// ---------------- launch 3 (CAPTURED): gather aggregation, warp per node ----------------
__global__ void k_gather(const float* __restrict__ x0, const float* __restrict__ x1) {
    int p = blockIdx.y;
    const float4* x4 = (const float4*)(p ? x1 : x0);
    const int*    csr  = g_csr[p];
    const float*  dinv = g_dinv[p];

    int gw = (blockIdx.x * blockDim.x + threadIdx.x) >> 5;
    int lane = threadIdx.x & 31;
    if (gw >= N_NODES) return;
    const int i = gw;
    const float di = dinv[i];

    float4 xi = x4[(size_t)i * 32 + lane];
    float w = di * di;
    float4 acc;
    acc.x = w * xi.x; acc.y = w * xi.y; acc.z = w * xi.z; acc.w = w * xi.w;

    int j = g_offs[p][i];
    const int s1 = g_offs[p][i + 1];
    for (; j + 4 <= s1; j += 4) {
        int sa = csr[j], sb = csr[j + 1], sc = csr[j + 2], sd = csr[j + 3];
        float wa = di * dinv[sa], wb = di * dinv[sb], wc = di * dinv[sc], wd = di * dinv[sd];
        float4 xa = x4[(size_t)sa * 32 + lane];
        float4 xb = x4[(size_t)sb * 32 + lane];
        float4 xc = x4[(size_t)sc * 32 + lane];
        float4 xd = x4[(size_t)sd * 32 + lane];
        acc.x += wa * xa.x + wb * xb.x + wc * xc.x + wd * xd.x;
        acc.y += wa * xa.y + wb * xb.y + wc * xc.y + wd * xd.y;
        acc.z += wa * xa.z + wb * xb.z + wc * xc.z + wd * xd.z;
        acc.w += wa * xa.w + wb * xb.w + wc * xc.w + wd * xd.w;
    }
    for (; j < s1; j++) {
        int s = csr[j];
        float ws = di * dinv[s];
        float4 xs = x4[(size_t)s * 32 + lane];
        acc.x += ws * xs.x; acc.y += ws * xs.y; acc.z += ws * xs.z; acc.w += ws * xs.w;
    }
    ((float4*)g_agg[p])[(size_t)i * 32 + lane] = acc;
}

// ---------------- launch 4: GEMM (FFMA2) + lrelu + segment_max epilogue ----------------
__global__ void __launch_bounds__(256, 2)
k_gemm_pool(const float* __restrict__ W0, const float* __restrict__ b0,
            const float* __restrict__ W1, const float* __restrict__ b1,
            const int* __restrict__ batch0, const int* __restrict__ batch1) {
    __shared__ float As[128][33];
    __shared__ __align__(16) float Ws[32][128];
    const int p = blockIdx.y;
    const float* __restrict__ W     = p ? W1 : W0;
    const float* __restrict__ bias  = p ? b1 : b0;
    const int*   __restrict__ batch = p ? batch1 : batch0;
    const float* __restrict__ agg   = g_agg[p];
    const int tx = threadIdx.x & 15;
    const int ty = threadIdx.x >> 4;
    const int row0 = blockIdx.x * 128;

    unsigned long long acc2[8][4];
    #pragma unroll
    for (int i = 0; i < 8; i++)
        #pragma unroll
        for (int j = 0; j < 4; j++) acc2[i][j] = 0ULL;

    for (int kb = 0; kb < 4; kb++) {
        #pragma unroll
        for (int it = 0; it < 4; it++) {
            int flat = threadIdx.x + it * 256;   // float4 index, 1024 total
            int r = flat >> 3, c4 = (flat & 7) * 4;
            int gm = row0 + r;
            float4 v = make_float4(0.f, 0.f, 0.f, 0.f);
            if (gm < N_NODES)
                v = *(const float4*)&agg[(size_t)gm * 128 + kb * 32 + c4];
            As[r][c4 + 0] = v.x; As[r][c4 + 1] = v.y; As[r][c4 + 2] = v.z; As[r][c4 + 3] = v.w;
        }
        #pragma unroll
        for (int it = 0; it < 4; it++) {
            int flat = threadIdx.x + it * 256;
            int r = flat >> 5, c4 = (flat & 31) * 4;
            *(float4*)&Ws[r][c4] = *(const float4*)&W[(size_t)(kb * 32 + r) * 128 + c4];
        }
        __syncthreads();
        #pragma unroll
        for (int k = 0; k < 32; k++) {
            float a[8];
            #pragma unroll
            for (int i = 0; i < 8; i++) a[i] = As[ty * 8 + i][k];
            unsigned long long b2[4];
            #pragma unroll
            for (int j = 0; j < 4; j++)
                b2[j] = *(const unsigned long long*)&Ws[k][tx * 8 + j * 2];
            #pragma unroll
            for (int i = 0; i < 8; i++) {
                unsigned long long av;
                unsigned ai = __float_as_uint(a[i]);
                asm("mov.b64 %0, {%1, %1};" : "=l"(av) : "r"(ai));
                #pragma unroll
                for (int j = 0; j < 4; j++) FMA_F32X2(acc2[i][j], av, b2[j]);
            }
        }
        __syncthreads();
    }

    // epilogue: reduce rows sharing a batch before atomics (lrelu monotone => commutes with max)
    float* pool = &g_pool[p * NB * DIM];
    const int r0 = row0 + ty * 8;
    const int rlast = r0 + 7;
    int btA = (r0 < N_NODES) ? batch[r0] : -1;
    int btB = (rlast < N_NODES) ? batch[rlast] : -2;
    const bool uni = (btA == btB);
    const int code = uni ? btA : -1;

    float m[8];
    #pragma unroll
    for (int j = 0; j < 8; j++) m[j] = -FLT_MAX;
    #pragma unroll
    for (int i = 0; i < 8; i++)
        #pragma unroll
        for (int j2 = 0; j2 < 4; j2++) {
            unsigned lo, hi;
            asm("mov.b64 {%0, %1}, %2;" : "=r"(lo), "=r"(hi) : "l"(acc2[i][j2]));
            m[2 * j2]     = fmaxf(m[2 * j2],     __uint_as_float(lo));
            m[2 * j2 + 1] = fmaxf(m[2 * j2 + 1], __uint_as_float(hi));
        }

    // merge with shfl-16 partner (same tx, adjacent ty) when batches match — uniform shfls
    const int ocode = __shfl_xor_sync(0xffffffffu, code, 16);
    const bool merged = (code >= 0) && (ocode == code);
    #pragma unroll
    for (int j = 0; j < 8; j++) {
        float om = __shfl_xor_sync(0xffffffffu, m[j], 16);
        if (merged) m[j] = fmaxf(m[j], om);
    }

    if (code >= 0) {
        if (!merged || (threadIdx.x & 16) == 0) {
            float* pr = &pool[code * DIM];
            #pragma unroll
            for (int j = 0; j < 8; j++) {
                int col = tx * 8 + j;
                atomicMaxFloat(&pr[col], lrelu(m[j] + bias[col]));
            }
        }
    } else {
        // mixed-batch (or partial) tile: per-row fallback
        #pragma unroll
        for (int i = 0; i < 8; i++) {
            int gm = r0 + i;
            if (gm >= N_NODES) continue;
            int bt = batch[gm];
            float* pr = &pool[bt * DIM];
            #pragma unroll
            for (int j2 = 0; j2 < 4; j2++) {
                unsigned lo, hi;
                asm("mov.b64 {%0, %1}, %2;" : "=r"(lo), "=r"(hi) : "l"(acc2[i][j2]));
                int c0 = tx * 8 + 2 * j2;
                atomicMaxFloat(&pr[c0],     lrelu(__uint_as_float(lo) + bias[c0]));
                atomicMaxFloat(&pr[c0 + 1], lrelu(__uint_as_float(hi) + bias[c0 + 1]));
            }
        }
    }
}

// ---------------- tail MLPs (tiny) ----------------
__global__ void k_fcp(const float* __restrict__ W1, const float* __restrict__ b1,
                      const float* __restrict__ W2, const float* __restrict__ b2) {
    int p = blockIdx.y, r = blockIdx.x, d = threadIdx.x;
    __shared__ float prow[128];
    prow[d] = g_pool[p * NB * DIM + r * 128 + d];
    __syncthreads();
    const float* W = p ? W2 : W1;
    const float* bb = p ? b2 : b1;
    float s = bb[d];
    #pragma unroll 8
    for (int k = 0; k < 128; k++) s += prow[k] * W[k * 128 + d];
    g_gp[p * NB * DIM + r * 128 + d] = lrelu(s);
}

__global__ void k_fc1(const float* __restrict__ W, const float* __restrict__ b) {
    int r = blockIdx.x, d = threadIdx.x;
    __shared__ float in[256];
    in[d] = (d < 128) ? g_gp[r * 128 + d] : g_gp[NB * DIM + r * 128 + (d - 128)];
    __syncthreads();
    float s = b[d];
    #pragma unroll 8
    for (int k = 0; k < 256; k++) s += in[k] * W[k * 256 + d];
    g_c1[r * 256 + d] = lrelu(s);
}

__global__ void k_fc2(const float* __restrict__ W, const float* __restrict__ b) {
    int r = blockIdx.x, d = threadIdx.x;
    __shared__ float in[256];
    for (int k = d; k < 256; k += 64) in[k] = g_c1[r * 256 + k];
    __syncthreads();
    float s = b[d];
    #pragma unroll 8
    for (int k = 0; k < 256; k++) s += in[k] * W[k * 64 + d];
    g_c2[r * 64 + d] = lrelu(s);
}

__global__ void k_out(const float* __restrict__ W, const float* __restrict__ b,
                      float* __restrict__ out) {
    int r = threadIdx.x;
    float s = b[0];
    #pragma unroll
    for (int k = 0; k < 64; k++) s += g_c2[r * 64 + k] * W[k];
    out[r] = 1.f / (1.f + expf(-s));
}

// ---------------- host launcher ----------------
extern "C" void kernel_launch(void* const* d_in, const int* in_sizes, int n_in,
                              void* d_out, int out_size) {
    int ix[2], ie[2], ib[2];
    if (in_sizes[1] == N_NODES * DIM) {
        ix[0] = 0; ix[1] = 1; ie[0] = 2; ie[1] = 3; ib[0] = 4; ib[1] = 5;   // dict order
    } else {
        ix[0] = 0; ie[0] = 1; ib[0] = 2; ix[1] = 3; ie[1] = 4; ib[1] = 5;   // signature order
    }
    const float* x0 = (const float*)d_in[ix[0]];
    const float* x1 = (const float*)d_in[ix[1]];
    const int* row0 = (const int*)d_in[ie[0]];
    const int* col0 = row0 + N_EDGES;
    const int* row1 = (const int*)d_in[ie[1]];
    const int* col1 = row1 + N_EDGES;
    const int* bat0 = (const int*)d_in[ib[0]];
    const int* bat1 = (const int*)d_in[ib[1]];

    const float* convW0 = (const float*)d_in[6];
    const float* convB0 = (const float*)d_in[7];
    const float* convW1 = (const float*)d_in[8];
    const float* convB1 = (const float*)d_in[9];
    const float* fcp1W = (const float*)d_in[10];
    const float* fcp1B = (const float*)d_in[11];
    const float* fcp2W = (const float*)d_in[12];
    const float* fcp2B = (const float*)d_in[13];
    const float* fc1W  = (const float*)d_in[14];
    const float* fc1B  = (const float*)d_in[15];
    const float* fc2W  = (const float*)d_in[16];
    const float* fc2B  = (const float*)d_in[17];
    const float* outW  = (const float*)d_in[18];
    const float* outB  = (const float*)d_in[19];

    void* zPtr = nullptr;
    cudaGetSymbolAddress(&zPtr, g_z);
    cudaMemsetAsync(zPtr, 0, sizeof(Zeroed));

    const int EB = (N_EDGES + 255) / 256;
    k_count<<<dim3(EB, 2), 256>>>(col0, col1);                               // launch 0
    k_scan<<<dim3(SCAN_BLOCKS, 2), 1024>>>();                                // launch 1
    k_fill<<<dim3(EB, 2), 256>>>(row0, col0, row1, col1);                    // launch 2
    k_gather<<<dim3((N_NODES * 32 + 255) / 256, 2), 256>>>(x0, x1);          // launch 3 (captured)
    k_gemm_pool<<<dim3((N_NODES + 127) / 128, 2), 256>>>(convW0, convB0, convW1, convB1, bat0, bat1);

    k_fcp<<<dim3(NB, 2), 128>>>(fcp1W, fcp1B, fcp2W, fcp2B);
    k_fc1<<<NB, 256>>>(fc1W, fc1B);
    k_fc2<<<NB, 64>>>(fc2W, fc2B);
    k_out<<<1, 128>>>(outW, outB, (float*)d_out);
}